// round 13
// baseline (speedup 1.0000x reference)
#include <cuda_runtime.h>
#include <cstdint>

#define HD   19      // hidden size
#define HJ   20      // padded row stride
#define DD   64      // input size
#define TPB  128
#define RPT  2       // batch rows per thread
#define RPB  (TPB * RPT)
#define NPART 1024

__device__ float g_partials[NPART];

struct Tables {
    float WiT[DD * HJ];   // [k][j] = Wi[j][k]
    float WrT[HD * HJ];   // [k][j] = Wr[j][k]
    float WoT[HD * HJ];   // [k][j] = Wo[j][k]
    float bi[HJ];
    float bo[HJ];
    float bdt[HJ];        // dt / tau_dyn
};
__device__ Tables g_tab;
#define TAB_F ((int)(sizeof(Tables) / 4))

static __device__ __forceinline__ float tanha(float v) {
    float r; asm("tanh.approx.f32 %0,%1;" : "=f"(r) : "f"(v)); return r;
}
// forced-scalar shared load (prevents LDS.128 re-vectorization)
static __device__ __forceinline__ float lds32(uint32_t a) {
    float r; asm("ld.shared.f32 %0,[%1];" : "=f"(r) : "r"(a)); return r;
}
static __device__ __forceinline__ uint32_t saddr(const void* p) {
    uint32_t a;
    asm("{.reg .u64 t; cvta.to.shared.u64 t,%1; cvt.u32.u64 %0,t;}"
        : "=r"(a) : "l"(p));
    return a;
}

// ---------- kernel A: per-block partial sums of |x| ----------
__global__ void __launch_bounds__(256) k_a_red(const float4* __restrict__ x, int n4) {
    float s = 0.f;
    for (int i = blockIdx.x * blockDim.x + threadIdx.x; i < n4;
         i += gridDim.x * blockDim.x) {
        float4 v = x[i];
        s += fabsf(v.x) + fabsf(v.y) + fabsf(v.z) + fabsf(v.w);
    }
#pragma unroll
    for (int o = 16; o > 0; o >>= 1) s += __shfl_down_sync(0xffffffffu, s, o);
    __shared__ float ws[8];
    int w = threadIdx.x >> 5, l = threadIdx.x & 31;
    if (l == 0) ws[w] = s;
    __syncthreads();
    if (threadIdx.x == 0) {
        float t = 0.f;
#pragma unroll
        for (int i = 0; i < 8; i++) t += ws[i];
        g_partials[blockIdx.x] = t;
    }
}

// ---------- kernel B: finish reduction + build transposed tables ----------
__global__ void __launch_bounds__(256) k_prep(
    const float* __restrict__ Wi, const float* __restrict__ bi,
    const float* __restrict__ Wr, const float* __restrict__ Wo,
    const float* __restrict__ bo, const float* __restrict__ tau,
    const float* __restrict__ ta, float invN)
{
    __shared__ float red[256];
    __shared__ float urg_s;
    int t = threadIdx.x;

    float s = 0.f;
    for (int i = t; i < NPART; i += 256) s += g_partials[i];
    red[t] = s;
    __syncthreads();
#pragma unroll
    for (int o = 128; o > 0; o >>= 1) {
        if (t < o) red[t] += red[t + o];
        __syncthreads();
    }
    if (t == 0) urg_s = fmaxf(red[0] * invN, 0.01f);

    float* gt = (float*)&g_tab;
    for (int i = t; i < TAB_F; i += 256) gt[i] = 0.f;
    __syncthreads();
    float urg = urg_s;

    for (int i = t; i < DD * HD; i += 256) {
        int k = i / HD, j = i % HD;
        g_tab.WiT[k * HJ + j] = Wi[j * DD + k];
    }
    for (int i = t; i < HD * HD; i += 256) {
        int k = i / HD, j = i % HD;
        g_tab.WrT[k * HJ + j] = Wr[j * HD + k];
        g_tab.WoT[k * HJ + j] = Wo[j * HD + k];
    }
    if (t < HD) {
        g_tab.bi[t] = bi[t];
        g_tab.bo[t] = bo[t];
        float td = tau[t] * (1.0f - ta[t]) + ta[t] / urg;
        td = fminf(fmaxf(td, 0.01f), 10.0f);
        g_tab.bdt[t] = 0.01f / td;
    }
}

// ---------- kernel C: RPT=2, 4 CTAs/SM, mapped in smem, scalar LDS ----------
__global__ void __launch_bounds__(TPB, 4)
k_main(const float* __restrict__ x, const int* __restrict__ steps_p,
       float* __restrict__ out, float* __restrict__ hout)
{
    __shared__ float sWi[DD * HJ];      // 5120 B
    __shared__ float sWr[HD * HJ];      // 1520 B
    __shared__ float sWo[HD * HJ];      // 1520 B
    __shared__ float sBi[HJ], sBo[HJ], sBd[HJ];
    __shared__ float mst[RPB * HD];     // mapped staging [j][r][tid]; then output

    const int tid = threadIdx.x;
    {
        const float* gt = (const float*)&g_tab;
        for (int i = tid; i < DD * HJ; i += TPB) sWi[i] = gt[i];
        const float* g1 = gt + DD * HJ;
        for (int i = tid; i < HD * HJ; i += TPB) sWr[i] = g1[i];
        const float* g2 = g1 + HD * HJ;
        for (int i = tid; i < HD * HJ; i += TPB) sWo[i] = g2[i];
        const float* g3 = g2 + HD * HJ;
        if (tid < HJ) {
            sBi[tid] = g3[tid];
            sBo[tid] = g3[HJ + tid];
            sBd[tid] = g3[2 * HJ + tid];
        }
    }
    __syncthreads();

    const uint32_t aWi = saddr(sWi);
    const uint32_t aWr = saddr(sWr);
    const uint32_t aWo = saddr(sWo);
    const uint32_t aBd = saddr(sBd);
    const uint32_t aM  = saddr(mst);

    const size_t row0 = (size_t)blockIdx.x * RPB + tid;

    // ---- phase 1: mapped = x @ Wi^T + bi -> smem (one row at a time) ----
#pragma unroll
    for (int r = 0; r < RPT; r++) {
        const float4* xr = (const float4*)(x + (row0 + (size_t)r * TPB) * DD);
        float m[HD];
#pragma unroll
        for (int j = 0; j < HD; j++) m[j] = sBi[j];
#pragma unroll 4
        for (int q = 0; q < DD / 4; q++) {
            float4 v = xr[q];
            float vv[4] = {v.x, v.y, v.z, v.w};
#pragma unroll
            for (int e = 0; e < 4; e++) {
                uint32_t wb = aWi + (uint32_t)((q * 4 + e) * HJ) * 4u;
                float xk = vv[e];
#pragma unroll
                for (int j = 0; j < HD; j++)
                    m[j] = fmaf(xk, lds32(wb + 4u * j), m[j]);
            }
        }
#pragma unroll
        for (int j = 0; j < HD; j++)
            mst[(j * RPT + r) * TPB + tid] = m[j];
    }
    // threads only read their own slots below; no block sync needed

    // ---- phase 2: recurrence ----
    float h0[HD], h1[HD];
#pragma unroll
    for (int j = 0; j < HD; j++) { h0[j] = 0.f; h1[j] = 0.f; }

    const int steps = *steps_p;
    for (int s = 0; s < steps; s++) {
        float a0[HD], a1[HD];
#pragma unroll
        for (int j = 0; j < HD; j++) {
            a0[j] = lds32(aM + 4u * ((j * RPT + 0) * TPB + tid));
            a1[j] = lds32(aM + 4u * ((j * RPT + 1) * TPB + tid));
        }
#pragma unroll
        for (int k = 0; k < HD; k++) {
            uint32_t wb = aWr + (uint32_t)(k * HJ) * 4u;
            float hk0 = h0[k], hk1 = h1[k];
#pragma unroll
            for (int j = 0; j < HD; j++) {
                float w = lds32(wb + 4u * j);
                a0[j] = fmaf(hk0, w, a0[j]);
                a1[j] = fmaf(hk1, w, a1[j]);
            }
        }
#pragma unroll
        for (int j = 0; j < HD; j++) {
            float b = lds32(aBd + 4u * j);
            h0[j] = fmaf(b, tanha(a0[j]) - h0[j], h0[j]);
            h1[j] = fmaf(b, tanha(a1[j]) - h1[j], h1[j]);
        }
    }

    // ---- phase 3: out = h @ Wo^T + bo ----
    float o0[HD], o1[HD];
#pragma unroll
    for (int j = 0; j < HD; j++) { o0[j] = sBo[j]; o1[j] = sBo[j]; }
#pragma unroll
    for (int k = 0; k < HD; k++) {
        uint32_t wb = aWo + (uint32_t)(k * HJ) * 4u;
        float hk0 = h0[k], hk1 = h1[k];
#pragma unroll
        for (int j = 0; j < HD; j++) {
            float w = lds32(wb + 4u * j);
            o0[j] = fmaf(hk0, w, o0[j]);
            o1[j] = fmaf(hk1, w, o1[j]);
        }
    }

    // ---- stage + coalesced stores (reuse mst) ----
    __syncthreads();
#pragma unroll
    for (int j = 0; j < HD; j++) {
        mst[tid * HD + j]         = o0[j];
        mst[(TPB + tid) * HD + j] = o1[j];
    }
    __syncthreads();
    {
        float4* go = (float4*)(out + (size_t)blockIdx.x * (RPB * HD));
        const float4* f4 = (const float4*)mst;
        for (int i = tid; i < RPB * HD / 4; i += TPB) go[i] = f4[i];
    }
    if (hout) {
        __syncthreads();
#pragma unroll
        for (int j = 0; j < HD; j++) {
            mst[tid * HD + j]         = h0[j];
            mst[(TPB + tid) * HD + j] = h1[j];
        }
        __syncthreads();
        float4* gh = (float4*)(hout + (size_t)blockIdx.x * (RPB * HD));
        const float4* f4 = (const float4*)mst;
        for (int i = tid; i < RPB * HD / 4; i += TPB) gh[i] = f4[i];
    }
}

extern "C" void kernel_launch(void* const* d_in, const int* in_sizes, int n_in,
                              void* d_out, int out_size) {
    const float* x   = (const float*)d_in[0];
    const float* Wi  = (const float*)d_in[1];
    const float* bi  = (const float*)d_in[2];
    const float* Wr  = (const float*)d_in[3];
    const float* Wo  = (const float*)d_in[4];
    const float* bo  = (const float*)d_in[5];
    const float* tau = (const float*)d_in[6];
    const float* ta  = (const float*)d_in[7];
    const int* steps = (const int*)d_in[8];

    const int nx = in_sizes[0];
    const int B  = nx / DD;

    float* out = (float*)d_out;
    long long bh = (long long)B * HD;
    float* hout = ((long long)out_size >= 2 * bh) ? (out + bh) : nullptr;

    k_a_red<<<NPART, 256>>>((const float4*)x, nx / 4);
    k_prep<<<1, 256>>>(Wi, bi, Wr, Wo, bo, tau, ta, 1.0f / (float)nx);
    k_main<<<B / RPB, TPB>>>(x, steps, out, hout);
}

// round 14
// speedup vs baseline: 4.4692x; 4.4692x over previous
#include <cuda_runtime.h>
#include <cstdint>

#define HD   19      // hidden size
#define HJ   20      // padded row stride
#define DD   64      // input size
#define TPB  128
#define RPT  2       // batch rows per thread
#define RPB  (TPB * RPT)
#define NPART 1024

__device__ float g_partials[NPART];

struct Tables {
    float WiT[DD * HJ];   // [k][j] = Wi[j][k]
    float WrT[HD * HJ];   // [k][j] = Wr[j][k]
    float WoT[HD * HJ];   // [k][j] = Wo[j][k]
    float bi[HJ];
    float bo[HJ];
    float bdt[HJ];        // dt / tau_dyn
};
__device__ Tables g_tab;            // staging (written by k_prep)
__constant__ Tables c_tab;          // uniform-path weights for k_main
#define TAB_F ((int)(sizeof(Tables) / 4))

static __device__ __forceinline__ float tanha(float v) {
    float r; asm("tanh.approx.f32 %0,%1;" : "=f"(r) : "f"(v)); return r;
}

// ---------- kernel A: per-block partial sums of |x| ----------
__global__ void __launch_bounds__(256) k_a_red(const float4* __restrict__ x, int n4) {
    float s = 0.f;
    for (int i = blockIdx.x * blockDim.x + threadIdx.x; i < n4;
         i += gridDim.x * blockDim.x) {
        float4 v = x[i];
        s += fabsf(v.x) + fabsf(v.y) + fabsf(v.z) + fabsf(v.w);
    }
#pragma unroll
    for (int o = 16; o > 0; o >>= 1) s += __shfl_down_sync(0xffffffffu, s, o);
    __shared__ float ws[8];
    int w = threadIdx.x >> 5, l = threadIdx.x & 31;
    if (l == 0) ws[w] = s;
    __syncthreads();
    if (threadIdx.x == 0) {
        float t = 0.f;
#pragma unroll
        for (int i = 0; i < 8; i++) t += ws[i];
        g_partials[blockIdx.x] = t;
    }
}

// ---------- kernel B: finish reduction + build transposed tables ----------
__global__ void __launch_bounds__(256) k_prep(
    const float* __restrict__ Wi, const float* __restrict__ bi,
    const float* __restrict__ Wr, const float* __restrict__ Wo,
    const float* __restrict__ bo, const float* __restrict__ tau,
    const float* __restrict__ ta, float invN)
{
    __shared__ float red[256];
    __shared__ float urg_s;
    int t = threadIdx.x;

    float s = 0.f;
    for (int i = t; i < NPART; i += 256) s += g_partials[i];
    red[t] = s;
    __syncthreads();
#pragma unroll
    for (int o = 128; o > 0; o >>= 1) {
        if (t < o) red[t] += red[t + o];
        __syncthreads();
    }
    if (t == 0) urg_s = fmaxf(red[0] * invN, 0.01f);

    float* gt = (float*)&g_tab;
    for (int i = t; i < TAB_F; i += 256) gt[i] = 0.f;
    __syncthreads();
    float urg = urg_s;

    for (int i = t; i < DD * HD; i += 256) {
        int k = i / HD, j = i % HD;
        g_tab.WiT[k * HJ + j] = Wi[j * DD + k];
    }
    for (int i = t; i < HD * HD; i += 256) {
        int k = i / HD, j = i % HD;
        g_tab.WrT[k * HJ + j] = Wr[j * HD + k];
        g_tab.WoT[k * HJ + j] = Wo[j * HD + k];
    }
    if (t < HD) {
        g_tab.bi[t] = bi[t];
        g_tab.bo[t] = bo[t];
        float td = tau[t] * (1.0f - ta[t]) + ta[t] / urg;
        td = fminf(fmaxf(td, 0.01f), 10.0f);
        g_tab.bdt[t] = 0.01f / td;
    }
}

// ---------- kernel C: constant-memory weights (uniform path), RPT=2 ----------
__global__ void __launch_bounds__(TPB)
k_main(const float* __restrict__ x, const int* __restrict__ steps_p,
       float* __restrict__ out, float* __restrict__ hout)
{
    __shared__ float mst[RPB * HD];     // mapped staging [j][r][tid]; then output

    const int tid = threadIdx.x;
    const size_t row0 = (size_t)blockIdx.x * RPB + tid;

    // ---- phase 1: mapped = x @ Wi^T + bi -> smem (one row at a time) ----
#pragma unroll
    for (int r = 0; r < RPT; r++) {
        const float4* xr = (const float4*)(x + (row0 + (size_t)r * TPB) * DD);
        float m[HD];
#pragma unroll
        for (int j = 0; j < HD; j++) m[j] = c_tab.bi[j];
#pragma unroll 4
        for (int q = 0; q < DD / 4; q++) {
            float4 v = xr[q];
            float vv[4] = {v.x, v.y, v.z, v.w};
#pragma unroll
            for (int e = 0; e < 4; e++) {
                const int k = q * 4 + e;
                float xk = vv[e];
#pragma unroll
                for (int j = 0; j < HD; j++)
                    m[j] = fmaf(xk, c_tab.WiT[k * HJ + j], m[j]);
            }
        }
#pragma unroll
        for (int j = 0; j < HD; j++)
            mst[(j * RPT + r) * TPB + tid] = m[j];
    }
    // threads only read their own slots below; no block sync needed

    // ---- phase 2: recurrence ----
    float h0[HD], h1[HD];
#pragma unroll
    for (int j = 0; j < HD; j++) { h0[j] = 0.f; h1[j] = 0.f; }

    const int steps = *steps_p;
    for (int s = 0; s < steps; s++) {
        float a0[HD], a1[HD];
#pragma unroll
        for (int j = 0; j < HD; j++) {
            a0[j] = mst[(j * RPT + 0) * TPB + tid];
            a1[j] = mst[(j * RPT + 1) * TPB + tid];
        }
#pragma unroll
        for (int k = 0; k < HD; k++) {
            float hk0 = h0[k], hk1 = h1[k];
#pragma unroll
            for (int j = 0; j < HD; j++) {
                float w = c_tab.WrT[k * HJ + j];
                a0[j] = fmaf(hk0, w, a0[j]);
                a1[j] = fmaf(hk1, w, a1[j]);
            }
        }
#pragma unroll
        for (int j = 0; j < HD; j++) {
            float b = c_tab.bdt[j];
            h0[j] = fmaf(b, tanha(a0[j]) - h0[j], h0[j]);
            h1[j] = fmaf(b, tanha(a1[j]) - h1[j], h1[j]);
        }
    }

    // ---- phase 3: out = h @ Wo^T + bo ----
    float o0[HD], o1[HD];
#pragma unroll
    for (int j = 0; j < HD; j++) { o0[j] = c_tab.bo[j]; o1[j] = c_tab.bo[j]; }
#pragma unroll
    for (int k = 0; k < HD; k++) {
        float hk0 = h0[k], hk1 = h1[k];
#pragma unroll
        for (int j = 0; j < HD; j++) {
            float w = c_tab.WoT[k * HJ + j];
            o0[j] = fmaf(hk0, w, o0[j]);
            o1[j] = fmaf(hk1, w, o1[j]);
        }
    }

    // ---- stage + coalesced stores (reuse mst) ----
    __syncthreads();
#pragma unroll
    for (int j = 0; j < HD; j++) {
        mst[tid * HD + j]         = o0[j];
        mst[(TPB + tid) * HD + j] = o1[j];
    }
    __syncthreads();
    {
        float4* go = (float4*)(out + (size_t)blockIdx.x * (RPB * HD));
        const float4* f4 = (const float4*)mst;
        for (int i = tid; i < RPB * HD / 4; i += TPB) go[i] = f4[i];
    }
    if (hout) {
        __syncthreads();
#pragma unroll
        for (int j = 0; j < HD; j++) {
            mst[tid * HD + j]         = h0[j];
            mst[(TPB + tid) * HD + j] = h1[j];
        }
        __syncthreads();
        float4* gh = (float4*)(hout + (size_t)blockIdx.x * (RPB * HD));
        const float4* f4 = (const float4*)mst;
        for (int i = tid; i < RPB * HD / 4; i += TPB) gh[i] = f4[i];
    }
}

extern "C" void kernel_launch(void* const* d_in, const int* in_sizes, int n_in,
                              void* d_out, int out_size) {
    const float* x   = (const float*)d_in[0];
    const float* Wi  = (const float*)d_in[1];
    const float* bi  = (const float*)d_in[2];
    const float* Wr  = (const float*)d_in[3];
    const float* Wo  = (const float*)d_in[4];
    const float* bo  = (const float*)d_in[5];
    const float* tau = (const float*)d_in[6];
    const float* ta  = (const float*)d_in[7];
    const int* steps = (const int*)d_in[8];

    const int nx = in_sizes[0];
    const int B  = nx / DD;

    float* out = (float*)d_out;
    long long bh = (long long)B * HD;
    float* hout = ((long long)out_size >= 2 * bh) ? (out + bh) : nullptr;

    static void* g_tab_addr = nullptr;      // deterministic symbol lookup
    if (!g_tab_addr) cudaGetSymbolAddress(&g_tab_addr, g_tab);

    k_a_red<<<NPART, 256>>>((const float4*)x, nx / 4);
    k_prep<<<1, 256>>>(Wi, bi, Wr, Wo, bo, tau, ta, 1.0f / (float)nx);
    // graph-capturable device-to-device copy into constant memory
    cudaMemcpyToSymbolAsync(c_tab, g_tab_addr, sizeof(Tables), 0,
                            cudaMemcpyDeviceToDevice, 0);
    k_main<<<B / RPB, TPB>>>(x, steps, out, hout);
}